// round 15
// baseline (speedup 1.0000x reference)
#include <cuda_runtime.h>

// SSIM, 7x7 VALID box, 128 x 384x384 fp32 pairs -> scalar mean.
//
// v15 = v14's pipeline with BOTH bandwidth levers composed:
//  - 18 bands x 21 rows: 2304 warps (15.6/SM, at the 128-reg/16-warp
//    ceiling) -> more MLP in flight (v13 showed this is thrash-safe
//    under __ldcs).
//  - __ldcs on all loads (L1 evict-first; retire-reloads hit L2).
//  - prefetch.global.L2 at distance 10 rows -> demand loads are L2 hits.

#define IMG_H 384
#define IMG_W 384
#define OUT_W 378
#define OUT_H 378
#define NIMG  128
#define NBAND 18
#define BAND_OUT 21
#define NTHREADS 64
#define WARPS_TOTAL (NIMG * NBAND)        // 2304
#define NCTA (WARPS_TOTAL / 2)            // 1152

__device__ float g_cta[NCTA];
__device__ unsigned int g_done = 0;

typedef unsigned long long u64;
static __device__ __forceinline__ u64 pk2(float lo, float hi) {
    u64 r; asm("mov.b64 %0,{%1,%2};" : "=l"(r) : "f"(lo), "f"(hi)); return r;
}
static __device__ __forceinline__ void upk2(float& lo, float& hi, u64 v) {
    asm("mov.b64 {%0,%1},%2;" : "=f"(lo), "=f"(hi) : "l"(v));
}
static __device__ __forceinline__ u64 add2(u64 a, u64 b) {
    u64 d; asm("add.rn.f32x2 %0,%1,%2;" : "=l"(d) : "l"(a), "l"(b)); return d;
}
static __device__ __forceinline__ u64 mul2(u64 a, u64 b) {
    u64 d; asm("mul.rn.f32x2 %0,%1,%2;" : "=l"(d) : "l"(a), "l"(b)); return d;
}
static __device__ __forceinline__ u64 fma2(u64 a, u64 b, u64 c) {
    u64 d; asm("fma.rn.f32x2 %0,%1,%2,%3;" : "=l"(d) : "l"(a), "l"(b), "l"(c)); return d;
}
static __device__ __forceinline__ u64 neg2(u64 a) {
    return a ^ 0x8000000080000000ULL;
}

#define ADMIT6(x0,x1,x2,y0,y1,y2) {                                         \
    u64 px[6] = { pk2((x0).x,(x0).y), pk2((x0).z,(x0).w),                   \
                  pk2((x1).x,(x1).y), pk2((x1).z,(x1).w),                   \
                  pk2((x2).x,(x2).y), pk2((x2).z,(x2).w) };                 \
    u64 py[6] = { pk2((y0).x,(y0).y), pk2((y0).z,(y0).w),                   \
                  pk2((y1).x,(y1).y), pk2((y1).z,(y1).w),                   \
                  pk2((y2).x,(y2).y), pk2((y2).z,(y2).w) };                 \
    _Pragma("unroll")                                                       \
    for (int _i = 0; _i < 6; ++_i) {                                        \
        X[_i]  = add2(X[_i],  px[_i]);                                      \
        Y[_i]  = add2(Y[_i],  py[_i]);                                      \
        Z[_i]  = fma2(px[_i], px[_i], fma2(py[_i], py[_i], Z[_i]));         \
        XY[_i] = fma2(px[_i], py[_i], XY[_i]);                              \
    } }

#define RETIRE6(x0,x1,x2,y0,y1,y2) {                                        \
    u64 px[6] = { pk2((x0).x,(x0).y), pk2((x0).z,(x0).w),                   \
                  pk2((x1).x,(x1).y), pk2((x1).z,(x1).w),                   \
                  pk2((x2).x,(x2).y), pk2((x2).z,(x2).w) };                 \
    u64 py[6] = { pk2((y0).x,(y0).y), pk2((y0).z,(y0).w),                   \
                  pk2((y1).x,(y1).y), pk2((y1).z,(y1).w),                   \
                  pk2((y2).x,(y2).y), pk2((y2).z,(y2).w) };                 \
    _Pragma("unroll")                                                       \
    for (int _i = 0; _i < 6; ++_i) {                                        \
        u64 nx = neg2(px[_i]), ny = neg2(py[_i]);                           \
        X[_i]  = add2(X[_i],  nx);                                          \
        Y[_i]  = add2(Y[_i],  ny);                                          \
        Z[_i]  = fma2(px[_i], nx, fma2(py[_i], ny, Z[_i]));                 \
        XY[_i] = fma2(px[_i], ny, XY[_i]);                                  \
    } }

#define SSIM_PAIR(WXp, WYp, WZp, WXYp, mask, accR) {                        \
    u64 p01 = mul2(WXp, WYp);                                               \
    u64 p00 = mul2(WXp, WXp);                                               \
    u64 p11 = mul2(WYp, WYp);                                               \
    u64 tt  = add2(p00, p11);                                               \
    u64 Axy = fma2(p01, c_ns1, WXYp);                                       \
    u64 AB  = fma2(tt,  c_ns1, WZp);                                        \
    u64 n1  = fma2(p01, c_kn1, c_C1);                                       \
    u64 n2  = fma2(Axy, c_kc2, c_C2);                                       \
    u64 d1  = fma2(tt,  c_ks2, c_C1);                                       \
    u64 d2  = fma2(AB,  c_kcv, c_C2);                                       \
    u64 num = mul2(n1, n2);                                                 \
    u64 den = mul2(d1, d2);                                                 \
    float na, nb, da, db;                                                   \
    upk2(na, nb, num); upk2(da, db, den);                                   \
    u64 rr = pk2(__fdividef(na, da), __fdividef(nb, db));                   \
    accR = fma2(mask, rr, accR); }

#define ADV_N(iTo, iFrom)                                                   \
    nx = cx + (xv[iTo]-xv[iFrom]); ny = cy + (yv[iTo]-yv[iFrom]);           \
    nz = cz + (zv[iTo]-zv[iFrom]); nw = cw + (wv[iTo]-wv[iFrom]);
#define ADV_C(iTo, iFrom)                                                   \
    cx = nx + (xv[iTo]-xv[iFrom]); cy = ny + (yv[iTo]-yv[iFrom]);           \
    cz = nz + (zv[iTo]-zv[iFrom]); cw = nw + (wv[iTo]-wv[iFrom]);
#define ADVB_N(j, iFrom)                                                    \
    nxB = cxB + (xu[j]-xv[iFrom]); nyB = cyB + (yu[j]-yv[iFrom]);           \
    nzB = czB + (zu[j]-zv[iFrom]); nwB = cwB + (wu[j]-wv[iFrom]);
#define ADVB_C(j, iFrom)                                                    \
    cxB = nxB + (xu[j]-xv[iFrom]); cyB = nyB + (yu[j]-yv[iFrom]);           \
    czB = nzB + (zu[j]-zv[iFrom]); cwB = nwB + (wu[j]-wv[iFrom]);

__global__ __launch_bounds__(NTHREADS, 8)
void ssim_v15_kernel(const float* __restrict__ pred,
                     const float* __restrict__ actual,
                     float* __restrict__ out) {
    const int gtid = blockIdx.x * blockDim.x + threadIdx.x;
    const int W    = gtid >> 5;
    const int lane = gtid & 31;
    const int wid  = threadIdx.x >> 5;

    const int img  = W / NBAND;
    const int band = W - img * NBAND;
    const int r0   = band * BAND_OUT;        // max 357
    const int c0   = 12 * lane;              // lane 31: cols 372..383

    const float* pX = pred   + (size_t)img * IMG_H * IMG_W + (size_t)r0 * IMG_W + c0;
    const float* pY = actual + (size_t)img * IMG_H * IMG_W + (size_t)r0 * IMG_W + c0;

    u64 X[6], Y[6], Z[6], XY[6];
    #pragma unroll
    for (int i = 0; i < 6; ++i) { X[i]=0; Y[i]=0; Z[i]=0; XY[i]=0; }

    // prologue: admit input rows 0..5 (streaming)
    #pragma unroll 1
    for (int k = 0; k < 6; ++k) {
        float4 x0 = __ldcs((const float4*)(pX + (size_t)k*IMG_W));
        float4 x1 = __ldcs((const float4*)(pX + (size_t)k*IMG_W + 4));
        float4 x2 = __ldcs((const float4*)(pX + (size_t)k*IMG_W + 8));
        float4 y0 = __ldcs((const float4*)(pY + (size_t)k*IMG_W));
        float4 y1 = __ldcs((const float4*)(pY + (size_t)k*IMG_W + 4));
        float4 y2 = __ldcs((const float4*)(pY + (size_t)k*IMG_W + 8));
        ADMIT6(x0,x1,x2,y0,y1,y2);
    }

    // prefetch input row 6 (streaming)
    float4 fx0 = __ldcs((const float4*)(pX + (size_t)6*IMG_W));
    float4 fx1 = __ldcs((const float4*)(pX + (size_t)6*IMG_W + 4));
    float4 fx2 = __ldcs((const float4*)(pX + (size_t)6*IMG_W + 8));
    float4 fy0 = __ldcs((const float4*)(pY + (size_t)6*IMG_W));
    float4 fy1 = __ldcs((const float4*)(pY + (size_t)6*IMG_W + 4));
    float4 fy2 = __ldcs((const float4*)(pY + (size_t)6*IMG_W + 8));

    const float s1   = 1.0f / 49.0f;
    const float covn = 49.0f / 48.0f;
    const u64 c_ns1 = pk2(-s1, -s1);
    const u64 c_kn1 = pk2(2.f * s1 * s1, 2.f * s1 * s1);
    const u64 c_ks2 = pk2(s1 * s1, s1 * s1);
    const u64 c_kcv = pk2(covn * s1, covn * s1);
    const u64 c_kc2 = pk2(2.f * covn * s1, 2.f * covn * s1);
    const u64 c_C1  = pk2(1e-4f, 1e-4f);
    const u64 c_C2  = pk2(9e-4f, 9e-4f);
    const u64 c_one = pk2(1.f, 1.f);
    const float mb  = (lane < 31) ? 1.f : 0.f;
    const u64 mB    = pk2(mb, mb);

    u64 accA = 0, accB = 0;

    #pragma unroll 1
    for (int r = 0; r < BAND_OUT; ++r) {
        // L2 prefetch of row r0+r+10 (clamped to last image row).
        {
            int rem = (IMG_H - 1) - (r0 + r);
            int off10 = rem < 10 ? rem : 10;
            asm volatile("prefetch.global.L2 [%0];"
                         :: "l"(pX + (size_t)off10 * IMG_W));
            asm volatile("prefetch.global.L2 [%0];"
                         :: "l"(pY + (size_t)off10 * IMG_W));
        }

        // retire-row loads (input row r0+r): L2 hit (streamed earlier)
        float4 rx0 = __ldcs((const float4*)(pX));
        float4 rx1 = __ldcs((const float4*)(pX + 4));
        float4 rx2 = __ldcs((const float4*)(pX + 8));
        float4 ry0 = __ldcs((const float4*)(pY));
        float4 ry1 = __ldcs((const float4*)(pY + 4));
        float4 ry2 = __ldcs((const float4*)(pY + 8));

        // admit prefetched row (input r0+r+6) — window r..r+6 complete
        ADMIT6(fx0,fx1,fx2,fy0,fy1,fy2);

        // prefetch next new row (r0+r+7; last iter re-loads r0+r+6, unused)
        {
            const int off = (r < BAND_OUT-1) ? 7 : 6;
            fx0 = __ldcs((const float4*)(pX + (size_t)off*IMG_W));
            fx1 = __ldcs((const float4*)(pX + (size_t)off*IMG_W + 4));
            fx2 = __ldcs((const float4*)(pX + (size_t)off*IMG_W + 8));
            fy0 = __ldcs((const float4*)(pY + (size_t)off*IMG_W));
            fy1 = __ldcs((const float4*)(pY + (size_t)off*IMG_W + 4));
            fy2 = __ldcs((const float4*)(pY + (size_t)off*IMG_W + 8));
        }

        // snapshot vertical sums as scalars
        float xv[12], yv[12], zv[12], wv[12];
        #pragma unroll
        for (int i = 0; i < 6; ++i) {
            upk2(xv[2*i], xv[2*i+1], X[i]);
            upk2(yv[2*i], yv[2*i+1], Y[i]);
            upk2(zv[2*i], zv[2*i+1], Z[i]);
            upk2(wv[2*i], wv[2*i+1], XY[i]);
        }

        // neighbor tail v12..v17 (lane+1's v0..v5)
        float xu[6], yu[6], zu[6], wu[6];
        #pragma unroll
        for (int j = 0; j < 6; ++j) {
            xu[j] = __shfl_down_sync(0xffffffffu, xv[j], 1);
            yu[j] = __shfl_down_sync(0xffffffffu, yv[j], 1);
            zu[j] = __shfl_down_sync(0xffffffffu, zv[j], 1);
            wu[j] = __shfl_down_sync(0xffffffffu, wv[j], 1);
        }

        // retire row r0+r (sums ready for next iteration)
        RETIRE6(rx0,rx1,rx2,ry0,ry1,ry2);

        // chain A: W0..W5
        float cx = ((xv[0]+xv[1])+(xv[2]+xv[3]))+((xv[4]+xv[5])+xv[6]);
        float cy = ((yv[0]+yv[1])+(yv[2]+yv[3]))+((yv[4]+yv[5])+yv[6]);
        float cz = ((zv[0]+zv[1])+(zv[2]+zv[3]))+((zv[4]+zv[5])+zv[6]);
        float cw = ((wv[0]+wv[1])+(wv[2]+wv[3]))+((wv[4]+wv[5])+wv[6]);
        float nx, ny, nz, nw;

        // chain B: fresh W6 = v6..v12
        float cxB = ((xv[6]+xv[7])+(xv[8]+xv[9]))+((xv[10]+xv[11])+xu[0]);
        float cyB = ((yv[6]+yv[7])+(yv[8]+yv[9]))+((yv[10]+yv[11])+yu[0]);
        float czB = ((zv[6]+zv[7])+(zv[8]+zv[9]))+((zv[10]+zv[11])+zu[0]);
        float cwB = ((wv[6]+wv[7])+(wv[8]+wv[9]))+((wv[10]+wv[11])+wu[0]);
        float nxB, nyB, nzB, nwB;

        ADV_N(7, 0);
        SSIM_PAIR(pk2(cx,nx), pk2(cy,ny), pk2(cz,nz), pk2(cw,nw), c_one, accA);
        ADVB_N(1, 6);
        SSIM_PAIR(pk2(cxB,nxB), pk2(cyB,nyB), pk2(czB,nzB), pk2(cwB,nwB), mB, accB);

        ADV_C(8, 1);
        ADV_N(9, 2);
        SSIM_PAIR(pk2(cx,nx), pk2(cy,ny), pk2(cz,nz), pk2(cw,nw), c_one, accA);
        ADVB_C(2, 7);
        ADVB_N(3, 8);
        SSIM_PAIR(pk2(cxB,nxB), pk2(cyB,nyB), pk2(czB,nzB), pk2(cwB,nwB), mB, accB);

        ADV_C(10, 3);
        ADV_N(11, 4);
        SSIM_PAIR(pk2(cx,nx), pk2(cy,ny), pk2(cz,nz), pk2(cw,nw), c_one, accA);
        ADVB_C(4, 9);
        ADVB_N(5, 10);
        SSIM_PAIR(pk2(cxB,nxB), pk2(cyB,nyB), pk2(czB,nzB), pk2(cwB,nwB), mB, accB);

        pX += IMG_W;  pY += IMG_W;
    }

    // lane-local total, deterministic warp reduction
    float a0, a1, b0, b1;
    upk2(a0, a1, accA); upk2(b0, b1, accB);
    float acc = (a0 + a1) + (b0 + b1);
    #pragma unroll
    for (int off = 16; off > 0; off >>= 1)
        acc += __shfl_xor_sync(0xffffffffu, acc, off);

    // CTA (2 warps) reduction, deterministic
    __shared__ float warp_sums[2];
    __shared__ unsigned int s_last;
    if (lane == 0) warp_sums[wid] = acc;
    __syncthreads();
    if (threadIdx.x == 0) {
        g_cta[blockIdx.x] = warp_sums[0] + warp_sums[1];
        __threadfence();
        unsigned int old = atomicAdd(&g_done, 1u);
        s_last = (old == NCTA - 1) ? 1u : 0u;
    }
    __syncthreads();

    // last CTA: deterministic fixed-order reduction of 1152 partials
    if (s_last) {
        __shared__ float red[NTHREADS];
        const int t = threadIdx.x;
        float c = 0.f;
        #pragma unroll
        for (int i = 0; i < NCTA / NTHREADS; ++i)    // 18 slots, fixed order
            c += g_cta[t + i * NTHREADS];
        red[t] = c;
        __syncthreads();
        #pragma unroll
        for (int s = NTHREADS / 2; s > 0; s >>= 1) {
            if (t < s) red[t] += red[t + s];
            __syncthreads();
        }
        if (t == 0) {
            out[0] = red[0] * (1.0f / ((float)NIMG * (float)OUT_W * (float)OUT_H));
            g_done = 0;   // reset for graph replay
        }
    }
}

extern "C" void kernel_launch(void* const* d_in, const int* in_sizes, int n_in,
                              void* d_out, int out_size) {
    const float* pred   = (const float*)d_in[0];
    const float* actual = (const float*)d_in[1];
    float* out = (float*)d_out;

    ssim_v15_kernel<<<NCTA, NTHREADS>>>(pred, actual, out);
}

// round 16
// speedup vs baseline: 1.4972x; 1.4972x over previous
#include <cuda_runtime.h>

// SSIM, 7x7 VALID box, 128 x 384x384 fp32 pairs -> scalar mean.
//
// v16 = v14 (14 bands x 27 rows, __ldcs, prefetch.L2@10, split chains)
// with DOUBLE-ROW iterations: all 24 demand LDG.128 of two output rows
// (2 retire + 2 new) issued as one front batch -> ~2x in-flight DRAM
// bytes per warp at unchanged request rate (the v15 failure showed the
// request-rate budget is full; this raises MLP without more requests).

#define IMG_H 384
#define IMG_W 384
#define OUT_W 378
#define OUT_H 378
#define NIMG  128
#define NBAND 14
#define BAND_OUT 27
#define NIT   13                          // double-row iters; +1 epilogue row
#define NTHREADS 64
#define WARPS_TOTAL (NIMG * NBAND)        // 1792
#define NCTA (WARPS_TOTAL / 2)            // 896

__device__ float g_cta[NCTA];
__device__ unsigned int g_done = 0;

typedef unsigned long long u64;
static __device__ __forceinline__ u64 pk2(float lo, float hi) {
    u64 r; asm("mov.b64 %0,{%1,%2};" : "=l"(r) : "f"(lo), "f"(hi)); return r;
}
static __device__ __forceinline__ void upk2(float& lo, float& hi, u64 v) {
    asm("mov.b64 {%0,%1},%2;" : "=f"(lo), "=f"(hi) : "l"(v));
}
static __device__ __forceinline__ u64 add2(u64 a, u64 b) {
    u64 d; asm("add.rn.f32x2 %0,%1,%2;" : "=l"(d) : "l"(a), "l"(b)); return d;
}
static __device__ __forceinline__ u64 mul2(u64 a, u64 b) {
    u64 d; asm("mul.rn.f32x2 %0,%1,%2;" : "=l"(d) : "l"(a), "l"(b)); return d;
}
static __device__ __forceinline__ u64 fma2(u64 a, u64 b, u64 c) {
    u64 d; asm("fma.rn.f32x2 %0,%1,%2,%3;" : "=l"(d) : "l"(a), "l"(b), "l"(c)); return d;
}
static __device__ __forceinline__ u64 neg2(u64 a) {
    return a ^ 0x8000000080000000ULL;
}

#define ADMIT6(x0,x1,x2,y0,y1,y2) {                                         \
    u64 px[6] = { pk2((x0).x,(x0).y), pk2((x0).z,(x0).w),                   \
                  pk2((x1).x,(x1).y), pk2((x1).z,(x1).w),                   \
                  pk2((x2).x,(x2).y), pk2((x2).z,(x2).w) };                 \
    u64 py[6] = { pk2((y0).x,(y0).y), pk2((y0).z,(y0).w),                   \
                  pk2((y1).x,(y1).y), pk2((y1).z,(y1).w),                   \
                  pk2((y2).x,(y2).y), pk2((y2).z,(y2).w) };                 \
    _Pragma("unroll")                                                       \
    for (int _i = 0; _i < 6; ++_i) {                                        \
        X[_i]  = add2(X[_i],  px[_i]);                                      \
        Y[_i]  = add2(Y[_i],  py[_i]);                                      \
        Z[_i]  = fma2(px[_i], px[_i], fma2(py[_i], py[_i], Z[_i]));         \
        XY[_i] = fma2(px[_i], py[_i], XY[_i]);                              \
    } }

#define RETIRE6(x0,x1,x2,y0,y1,y2) {                                        \
    u64 px[6] = { pk2((x0).x,(x0).y), pk2((x0).z,(x0).w),                   \
                  pk2((x1).x,(x1).y), pk2((x1).z,(x1).w),                   \
                  pk2((x2).x,(x2).y), pk2((x2).z,(x2).w) };                 \
    u64 py[6] = { pk2((y0).x,(y0).y), pk2((y0).z,(y0).w),                   \
                  pk2((y1).x,(y1).y), pk2((y1).z,(y1).w),                   \
                  pk2((y2).x,(y2).y), pk2((y2).z,(y2).w) };                 \
    _Pragma("unroll")                                                       \
    for (int _i = 0; _i < 6; ++_i) {                                        \
        u64 nx = neg2(px[_i]), ny = neg2(py[_i]);                           \
        X[_i]  = add2(X[_i],  nx);                                          \
        Y[_i]  = add2(Y[_i],  ny);                                          \
        Z[_i]  = fma2(px[_i], nx, fma2(py[_i], ny, Z[_i]));                 \
        XY[_i] = fma2(px[_i], ny, XY[_i]);                                  \
    } }

#define SSIM_PAIR(WXp, WYp, WZp, WXYp, mask, accR) {                        \
    u64 p01 = mul2(WXp, WYp);                                               \
    u64 p00 = mul2(WXp, WXp);                                               \
    u64 p11 = mul2(WYp, WYp);                                               \
    u64 tt  = add2(p00, p11);                                               \
    u64 Axy = fma2(p01, c_ns1, WXYp);                                       \
    u64 AB  = fma2(tt,  c_ns1, WZp);                                        \
    u64 n1  = fma2(p01, c_kn1, c_C1);                                       \
    u64 n2  = fma2(Axy, c_kc2, c_C2);                                       \
    u64 d1  = fma2(tt,  c_ks2, c_C1);                                       \
    u64 d2  = fma2(AB,  c_kcv, c_C2);                                       \
    u64 num = mul2(n1, n2);                                                 \
    u64 den = mul2(d1, d2);                                                 \
    float na, nb, da, db;                                                   \
    upk2(na, nb, num); upk2(da, db, den);                                   \
    u64 rr = pk2(__fdividef(na, da), __fdividef(nb, db));                   \
    accR = fma2(mask, rr, accR); }

#define ADV_N(iTo, iFrom)                                                   \
    nx = cx + (xv[iTo]-xv[iFrom]); ny = cy + (yv[iTo]-yv[iFrom]);           \
    nz = cz + (zv[iTo]-zv[iFrom]); nw = cw + (wv[iTo]-wv[iFrom]);
#define ADV_C(iTo, iFrom)                                                   \
    cx = nx + (xv[iTo]-xv[iFrom]); cy = ny + (yv[iTo]-yv[iFrom]);           \
    cz = nz + (zv[iTo]-zv[iFrom]); cw = nw + (wv[iTo]-wv[iFrom]);
#define ADVB_N(j, iFrom)                                                    \
    nxB = cxB + (xu[j]-xv[iFrom]); nyB = cyB + (yu[j]-yv[iFrom]);           \
    nzB = czB + (zu[j]-zv[iFrom]); nwB = cwB + (wu[j]-wv[iFrom]);
#define ADVB_C(j, iFrom)                                                    \
    cxB = nxB + (xu[j]-xv[iFrom]); cyB = nyB + (yu[j]-yv[iFrom]);           \
    czB = nzB + (zu[j]-zv[iFrom]); cwB = nwB + (wu[j]-wv[iFrom]);

// snapshot + neighbor shuffles + split-chain horizontal + SSIM accumulate
#define ROW_MATH() {                                                        \
    float xv[12], yv[12], zv[12], wv[12];                                   \
    _Pragma("unroll")                                                       \
    for (int _i = 0; _i < 6; ++_i) {                                        \
        upk2(xv[2*_i], xv[2*_i+1], X[_i]);                                  \
        upk2(yv[2*_i], yv[2*_i+1], Y[_i]);                                  \
        upk2(zv[2*_i], zv[2*_i+1], Z[_i]);                                  \
        upk2(wv[2*_i], wv[2*_i+1], XY[_i]);                                 \
    }                                                                       \
    float xu[6], yu[6], zu[6], wu[6];                                       \
    _Pragma("unroll")                                                       \
    for (int _j = 0; _j < 6; ++_j) {                                        \
        xu[_j] = __shfl_down_sync(0xffffffffu, xv[_j], 1);                  \
        yu[_j] = __shfl_down_sync(0xffffffffu, yv[_j], 1);                  \
        zu[_j] = __shfl_down_sync(0xffffffffu, zv[_j], 1);                  \
        wu[_j] = __shfl_down_sync(0xffffffffu, wv[_j], 1);                  \
    }                                                                       \
    float cx = ((xv[0]+xv[1])+(xv[2]+xv[3]))+((xv[4]+xv[5])+xv[6]);         \
    float cy = ((yv[0]+yv[1])+(yv[2]+yv[3]))+((yv[4]+yv[5])+yv[6]);         \
    float cz = ((zv[0]+zv[1])+(zv[2]+zv[3]))+((zv[4]+zv[5])+zv[6]);         \
    float cw = ((wv[0]+wv[1])+(wv[2]+wv[3]))+((wv[4]+wv[5])+wv[6]);         \
    float nx, ny, nz, nw;                                                   \
    float cxB = ((xv[6]+xv[7])+(xv[8]+xv[9]))+((xv[10]+xv[11])+xu[0]);      \
    float cyB = ((yv[6]+yv[7])+(yv[8]+yv[9]))+((yv[10]+yv[11])+yu[0]);      \
    float czB = ((zv[6]+zv[7])+(zv[8]+zv[9]))+((zv[10]+zv[11])+zu[0]);      \
    float cwB = ((wv[6]+wv[7])+(wv[8]+wv[9]))+((wv[10]+wv[11])+wu[0]);      \
    float nxB, nyB, nzB, nwB;                                               \
    ADV_N(7, 0);                                                            \
    SSIM_PAIR(pk2(cx,nx), pk2(cy,ny), pk2(cz,nz), pk2(cw,nw), c_one, accA); \
    ADVB_N(1, 6);                                                           \
    SSIM_PAIR(pk2(cxB,nxB), pk2(cyB,nyB), pk2(czB,nzB), pk2(cwB,nwB), mB, accB); \
    ADV_C(8, 1);                                                            \
    ADV_N(9, 2);                                                            \
    SSIM_PAIR(pk2(cx,nx), pk2(cy,ny), pk2(cz,nz), pk2(cw,nw), c_one, accA); \
    ADVB_C(2, 7);                                                           \
    ADVB_N(3, 8);                                                           \
    SSIM_PAIR(pk2(cxB,nxB), pk2(cyB,nyB), pk2(czB,nzB), pk2(cwB,nwB), mB, accB); \
    ADV_C(10, 3);                                                           \
    ADV_N(11, 4);                                                           \
    SSIM_PAIR(pk2(cx,nx), pk2(cy,ny), pk2(cz,nz), pk2(cw,nw), c_one, accA); \
    ADVB_C(4, 9);                                                           \
    ADVB_N(5, 10);                                                          \
    SSIM_PAIR(pk2(cxB,nxB), pk2(cyB,nyB), pk2(czB,nzB), pk2(cwB,nwB), mB, accB); \
    }

__global__ __launch_bounds__(NTHREADS, 6)
void ssim_v16_kernel(const float* __restrict__ pred,
                     const float* __restrict__ actual,
                     float* __restrict__ out) {
    const int gtid = blockIdx.x * blockDim.x + threadIdx.x;
    const int W    = gtid >> 5;
    const int lane = gtid & 31;
    const int wid  = threadIdx.x >> 5;

    const int img  = W / NBAND;
    const int band = W - img * NBAND;
    const int r0   = band * BAND_OUT;        // max 351; touches rows <= r0+32
    const int c0   = 12 * lane;

    const float* pX = pred   + (size_t)img * IMG_H * IMG_W + (size_t)r0 * IMG_W + c0;
    const float* pY = actual + (size_t)img * IMG_H * IMG_W + (size_t)r0 * IMG_W + c0;

    u64 X[6], Y[6], Z[6], XY[6];
    #pragma unroll
    for (int i = 0; i < 6; ++i) { X[i]=0; Y[i]=0; Z[i]=0; XY[i]=0; }

    // prologue: admit rows 0..5
    #pragma unroll 1
    for (int k = 0; k < 6; ++k) {
        float4 x0 = __ldcs((const float4*)(pX + (size_t)k*IMG_W));
        float4 x1 = __ldcs((const float4*)(pX + (size_t)k*IMG_W + 4));
        float4 x2 = __ldcs((const float4*)(pX + (size_t)k*IMG_W + 8));
        float4 y0 = __ldcs((const float4*)(pY + (size_t)k*IMG_W));
        float4 y1 = __ldcs((const float4*)(pY + (size_t)k*IMG_W + 4));
        float4 y2 = __ldcs((const float4*)(pY + (size_t)k*IMG_W + 8));
        ADMIT6(x0,x1,x2,y0,y1,y2);
    }

    // prefetch rows 6 (A) and 7 (B)
    float4 fAx0 = __ldcs((const float4*)(pX + (size_t)6*IMG_W));
    float4 fAx1 = __ldcs((const float4*)(pX + (size_t)6*IMG_W + 4));
    float4 fAx2 = __ldcs((const float4*)(pX + (size_t)6*IMG_W + 8));
    float4 fAy0 = __ldcs((const float4*)(pY + (size_t)6*IMG_W));
    float4 fAy1 = __ldcs((const float4*)(pY + (size_t)6*IMG_W + 4));
    float4 fAy2 = __ldcs((const float4*)(pY + (size_t)6*IMG_W + 8));
    float4 fBx0 = __ldcs((const float4*)(pX + (size_t)7*IMG_W));
    float4 fBx1 = __ldcs((const float4*)(pX + (size_t)7*IMG_W + 4));
    float4 fBx2 = __ldcs((const float4*)(pX + (size_t)7*IMG_W + 8));
    float4 fBy0 = __ldcs((const float4*)(pY + (size_t)7*IMG_W));
    float4 fBy1 = __ldcs((const float4*)(pY + (size_t)7*IMG_W + 4));
    float4 fBy2 = __ldcs((const float4*)(pY + (size_t)7*IMG_W + 8));

    const float s1   = 1.0f / 49.0f;
    const float covn = 49.0f / 48.0f;
    const u64 c_ns1 = pk2(-s1, -s1);
    const u64 c_kn1 = pk2(2.f * s1 * s1, 2.f * s1 * s1);
    const u64 c_ks2 = pk2(s1 * s1, s1 * s1);
    const u64 c_kcv = pk2(covn * s1, covn * s1);
    const u64 c_kc2 = pk2(2.f * covn * s1, 2.f * covn * s1);
    const u64 c_C1  = pk2(1e-4f, 1e-4f);
    const u64 c_C2  = pk2(9e-4f, 9e-4f);
    const u64 c_one = pk2(1.f, 1.f);
    const float mb  = (lane < 31) ? 1.f : 0.f;
    const u64 mB    = pk2(mb, mb);

    u64 accA = 0, accB = 0;

    // 13 double-row iterations: output rows 0..25
    #pragma unroll 1
    for (int it = 0; it < NIT; ++it) {
        // ---- front batch: all demand loads for both rows ----
        float4 rAx0 = __ldcs((const float4*)(pX));
        float4 rAx1 = __ldcs((const float4*)(pX + 4));
        float4 rAx2 = __ldcs((const float4*)(pX + 8));
        float4 rAy0 = __ldcs((const float4*)(pY));
        float4 rAy1 = __ldcs((const float4*)(pY + 4));
        float4 rAy2 = __ldcs((const float4*)(pY + 8));
        float4 rBx0 = __ldcs((const float4*)(pX + IMG_W));
        float4 rBx1 = __ldcs((const float4*)(pX + IMG_W + 4));
        float4 rBx2 = __ldcs((const float4*)(pX + IMG_W + 8));
        float4 rBy0 = __ldcs((const float4*)(pY + IMG_W));
        float4 rBy1 = __ldcs((const float4*)(pY + IMG_W + 4));
        float4 rBy2 = __ldcs((const float4*)(pY + IMG_W + 8));

        // L2 prefetch rows r+10, r+11 (clamped to row 32 of the band)
        {
            int r = 2 * it;
            int oA = r + 10 > 32 ? 32 : r + 10;
            int oB = r + 11 > 32 ? 32 : r + 11;
            asm volatile("prefetch.global.L2 [%0];" :: "l"(pX + (size_t)(oA - r) * IMG_W));
            asm volatile("prefetch.global.L2 [%0];" :: "l"(pY + (size_t)(oA - r) * IMG_W));
            asm volatile("prefetch.global.L2 [%0];" :: "l"(pX + (size_t)(oB - r) * IMG_W));
            asm volatile("prefetch.global.L2 [%0];" :: "l"(pY + (size_t)(oB - r) * IMG_W));
        }

        // ---- row r: admit r+6, math, retire r ----
        ADMIT6(fAx0,fAx1,fAx2,fAy0,fAy1,fAy2);
        ROW_MATH();
        RETIRE6(rAx0,rAx1,rAx2,rAy0,rAy1,rAy2);

        // ---- row r+1: admit r+7, math, retire r+1 ----
        ADMIT6(fBx0,fBx1,fBx2,fBy0,fBy1,fBy2);
        ROW_MATH();
        RETIRE6(rBx0,rBx1,rBx2,rBy0,rBy1,rBy2);

        // ---- prefetch rows r+8, r+9 for next iteration ----
        {
            const int offB = (it < NIT - 1) ? 9 : 8;   // avoid OOB at last iter
            fAx0 = __ldcs((const float4*)(pX + (size_t)8*IMG_W));
            fAx1 = __ldcs((const float4*)(pX + (size_t)8*IMG_W + 4));
            fAx2 = __ldcs((const float4*)(pX + (size_t)8*IMG_W + 8));
            fAy0 = __ldcs((const float4*)(pY + (size_t)8*IMG_W));
            fAy1 = __ldcs((const float4*)(pY + (size_t)8*IMG_W + 4));
            fAy2 = __ldcs((const float4*)(pY + (size_t)8*IMG_W + 8));
            fBx0 = __ldcs((const float4*)(pX + (size_t)offB*IMG_W));
            fBx1 = __ldcs((const float4*)(pX + (size_t)offB*IMG_W + 4));
            fBx2 = __ldcs((const float4*)(pX + (size_t)offB*IMG_W + 8));
            fBy0 = __ldcs((const float4*)(pY + (size_t)offB*IMG_W));
            fBy1 = __ldcs((const float4*)(pY + (size_t)offB*IMG_W + 4));
            fBy2 = __ldcs((const float4*)(pY + (size_t)offB*IMG_W + 8));
        }

        pX += 2 * IMG_W;  pY += 2 * IMG_W;
    }

    // epilogue: output row 26 (window rows 26..32; fA holds row 32)
    {
        ADMIT6(fAx0,fAx1,fAx2,fAy0,fAy1,fAy2);
        ROW_MATH();
    }

    // lane-local total, deterministic warp reduction
    float a0, a1, b0, b1;
    upk2(a0, a1, accA); upk2(b0, b1, accB);
    float acc = (a0 + a1) + (b0 + b1);
    #pragma unroll
    for (int off = 16; off > 0; off >>= 1)
        acc += __shfl_xor_sync(0xffffffffu, acc, off);

    // CTA (2 warps) reduction, deterministic
    __shared__ float warp_sums[2];
    __shared__ unsigned int s_last;
    if (lane == 0) warp_sums[wid] = acc;
    __syncthreads();
    if (threadIdx.x == 0) {
        g_cta[blockIdx.x] = warp_sums[0] + warp_sums[1];
        __threadfence();
        unsigned int old = atomicAdd(&g_done, 1u);
        s_last = (old == NCTA - 1) ? 1u : 0u;
    }
    __syncthreads();

    // last CTA: deterministic fixed-order reduction of 896 partials
    if (s_last) {
        __shared__ float red[NTHREADS];
        const int t = threadIdx.x;
        float c = 0.f;
        #pragma unroll
        for (int i = 0; i < NCTA / NTHREADS; ++i)    // 14 slots, fixed order
            c += g_cta[t + i * NTHREADS];
        red[t] = c;
        __syncthreads();
        #pragma unroll
        for (int s = NTHREADS / 2; s > 0; s >>= 1) {
            if (t < s) red[t] += red[t + s];
            __syncthreads();
        }
        if (t == 0) {
            out[0] = red[0] * (1.0f / ((float)NIMG * (float)OUT_W * (float)OUT_H));
            g_done = 0;   // reset for graph replay
        }
    }
}

extern "C" void kernel_launch(void* const* d_in, const int* in_sizes, int n_in,
                              void* d_out, int out_size) {
    const float* pred   = (const float*)d_in[0];
    const float* actual = (const float*)d_in[1];
    float* out = (float*)d_out;

    ssim_v16_kernel<<<NCTA, NTHREADS>>>(pred, actual, out);
}